// round 2
// baseline (speedup 1.0000x reference)
#include <cuda_runtime.h>
#include <cstdint>

#define N_NODES 50000
#define NE      640000
#define F       128
#define NG      256
#define NCLS    10
#define NLAYERS 3

// ---------------- scratch (static device globals; no allocations) ----------
__device__ __align__(16) float g_x  [N_NODES * F];   // working node features
__device__ __align__(16) float g_h  [N_NODES * F];   // GEMM output
__device__ __align__(16) float g_agg[N_NODES * F];   // aggregation buffer
__device__ float g_att [N_NODES];
__device__ float g_dinv[N_NODES];
__device__ float g_deg [N_NODES];
__device__ float g_colsum[F];
__device__ float g_colsq [F];
__device__ float g_rep[NG * 3 * F];
__device__ int   g_goff[NG + 1];
__device__ int   g_is64_edge;
__device__ int   g_is64_batch;

// ---------------- index dtype detection ------------------------------------
// JAX may silently downcast requested int64 -> int32. Element counts are the
// same either way, so probe values. int32 data read as int64 combines two
// random node ids -> >= 2^32 unless the high word is 0 (p ~ 2e-5 per sample).
__global__ void k_detect(const void* edge, const void* batch) {
    int ok = 1;
    for (int t = 0; t < 8; t++) {
        // int64 index t*79999+7 < 640000 -> in-bounds under both layouts
        long long v = ((const long long*)edge)[t * 79999 + 7];
        if (v < 0 || v >= N_NODES) ok = 0;
    }
    g_is64_edge = ok;
    int okb = 1;
    for (int t = 0; t < 8; t++) {
        // mid-array so the aliased high word is a nonzero graph id
        long long v = ((const long long*)batch)[12000 + t * 137];  // < 25000
        if (v < 0 || v >= NG) okb = 0;
    }
    g_is64_batch = okb;
}

__device__ __forceinline__ int ldidx(const void* p, long long i, int is64) {
    return is64 ? (int)((const long long*)p)[i] : ((const int*)p)[i];
}

// ---------------- init ------------------------------------------------------
__global__ void k_init() {
    int i = blockIdx.x * blockDim.x + threadIdx.x;
    if (i < F) { g_colsum[i] = 0.f; g_colsq[i] = 0.f; }
    if (i < NG * 3 * F) g_rep[i] = 0.f;
    if (i < N_NODES) g_deg[i] = 1.0f;   // self loop
}

// ---------------- BN column stats ------------------------------------------
__global__ void k_bnstats(const float* __restrict__ X) {
    int f  = threadIdx.x;          // 128 threads = feature
    int r0 = blockIdx.x * 256;
    float s = 0.f, q = 0.f;
    for (int r = 0; r < 256; r++) {
        int row = r0 + r;
        if (row >= N_NODES) break;
        float v = X[(size_t)row * F + f];
        s += v; q += v * v;
    }
    atomicAdd(&g_colsum[f], s);
    atomicAdd(&g_colsq[f], q);
}

// ---------------- degree (self-loops pre-counted as 1) ---------------------
__global__ void k_deg(const void* edge) {
    int e = blockIdx.x * blockDim.x + threadIdx.x;
    if (e >= NE) return;
    int is64 = g_is64_edge;
    int s = ldidx(edge, e, is64);
    int d = ldidx(edge, (long long)NE + e, is64);
    if (s != d) atomicAdd(&g_deg[d], 1.0f);
}

// ---------------- BN apply + dinv (vectorized float4) ----------------------
__global__ void k_bnapply(const float* __restrict__ X,
                          const float* __restrict__ gamma,
                          const float* __restrict__ beta) {
    int i = blockIdx.x * blockDim.x + threadIdx.x;   // float4 index
    const float invN = 1.0f / (float)N_NODES;
    if (i < N_NODES * (F / 4)) {
        int f0 = (i & 31) * 4;
        float4 v = ((const float4*)X)[i];
        float o[4]; float in[4] = {v.x, v.y, v.z, v.w};
        #pragma unroll
        for (int c = 0; c < 4; c++) {
            int f = f0 + c;
            float mu  = g_colsum[f] * invN;
            float var = g_colsq[f] * invN - mu * mu;
            o[c] = (in[c] - mu) / sqrtf(var + 1e-5f) * gamma[f] + beta[f];
        }
        ((float4*)g_x)[i] = make_float4(o[0], o[1], o[2], o[3]);
    }
    if (i < N_NODES) g_dinv[i] = rsqrtf(g_deg[i]);
}

// ---------------- per-graph offsets (batch sorted) -------------------------
__global__ void k_goff(const void* batch) {
    int g = blockIdx.x * blockDim.x + threadIdx.x;
    if (g > NG) return;
    int is64 = g_is64_batch;
    int lo = 0, hi = N_NODES;
    while (lo < hi) {
        int mid = (lo + hi) >> 1;
        long long v = is64 ? ((const long long*)batch)[mid]
                           : (long long)((const int*)batch)[mid];
        if (v < g) lo = mid + 1; else hi = mid;
    }
    g_goff[g] = lo;
}

// ------ GEMM: g_h = g_x @ W; fused epilogue also writes g_agg = dinv^2 * h -
#define BM 64
__global__ void __launch_bounds__(256) k_gemm(const float* __restrict__ W) {
    __shared__ float Xs[BM * 128];   // 32 KB
    __shared__ float Ws[32 * 128];   // 16 KB
    int tid = threadIdx.x;
    int m0  = blockIdx.x * BM;

    {   // stage X tile
        const float4* src = (const float4*)(g_x + (size_t)m0 * F);
        float4* dst = (float4*)Xs;
        for (int i = tid; i < BM * 32; i += 256) {
            int row = i >> 5;
            float4 v = make_float4(0.f, 0.f, 0.f, 0.f);
            if (m0 + row < N_NODES) v = src[i];
            dst[i] = v;
        }
    }
    int tx = tid & 31, ty = tid >> 5;
    float acc[8][4];
    #pragma unroll
    for (int r = 0; r < 8; r++)
        #pragma unroll
        for (int c = 0; c < 4; c++) acc[r][c] = 0.f;

    for (int kc = 0; kc < 128; kc += 32) {
        __syncthreads();
        const float4* wsrc = (const float4*)(W + (size_t)kc * 128);
        float4* wdst = (float4*)Ws;
        for (int i = tid; i < 1024; i += 256) wdst[i] = wsrc[i];
        __syncthreads();
        #pragma unroll
        for (int k = 0; k < 32; k++) {
            float4 b = ((const float4*)Ws)[k * 32 + tx];
            #pragma unroll
            for (int r = 0; r < 8; r++) {
                float a = Xs[(ty * 8 + r) * 128 + kc + k];   // warp-broadcast
                acc[r][0] += a * b.x; acc[r][1] += a * b.y;
                acc[r][2] += a * b.z; acc[r][3] += a * b.w;
            }
        }
    }
    #pragma unroll
    for (int r = 0; r < 8; r++) {
        int row = m0 + ty * 8 + r;
        if (row < N_NODES) {
            float4 v = make_float4(acc[r][0], acc[r][1], acc[r][2], acc[r][3]);
            ((float4*)(g_h + (size_t)row * F))[tx] = v;
            float di = g_dinv[row];            // self-loop term, fused
            float w = di * di;
            float4 a = make_float4(v.x * w, v.y * w, v.z * w, v.w * w);
            ((float4*)(g_agg + (size_t)row * F))[tx] = a;
        }
    }
}

// ---------------- edge scatter: warp per edge, red.v4 ----------------------
__global__ void __launch_bounds__(256) k_scatter(const void* edge) {
    int gw   = (blockIdx.x * blockDim.x + threadIdx.x) >> 5;
    int lane = threadIdx.x & 31;
    if (gw >= NE) return;
    int is64 = g_is64_edge;
    int s = ldidx(edge, gw, is64);
    int d = ldidx(edge, (long long)NE + gw, is64);
    if (s == d) return;                      // ew = 0 for original self loops
    float w = g_dinv[s] * g_dinv[d];
    float4 v = ((const float4*)(g_h + (size_t)s * F))[lane];
    v.x *= w; v.y *= w; v.z *= w; v.w *= w;
    float* dst = g_agg + (size_t)d * F + lane * 4;
    asm volatile("red.global.add.v4.f32 [%0], {%1,%2,%3,%4};"
                 :: "l"(dst), "f"(v.x), "f"(v.y), "f"(v.z), "f"(v.w)
                 : "memory");
}

// ---------------- squash + attention score: warp per node ------------------
__global__ void k_squash(const float* __restrict__ bias,
                         const float* __restrict__ wa) {
    int node = (blockIdx.x * blockDim.x + threadIdx.x) >> 5;
    int lane = threadIdx.x & 31;
    if (node >= N_NODES) return;
    float4 v  = ((const float4*)(g_agg + (size_t)node * F))[lane];
    float4 bb = ((const float4*)bias)[lane];
    v.x += bb.x; v.y += bb.y; v.z += bb.z; v.w += bb.w;
    float n2 = v.x * v.x + v.y * v.y + v.z * v.z + v.w * v.w;
    #pragma unroll
    for (int o = 16; o > 0; o >>= 1) n2 += __shfl_xor_sync(0xffffffffu, n2, o);
    float scale = n2 / ((1.0f + n2) * sqrtf(n2 + 1e-8f));
    v.x *= scale; v.y *= scale; v.z *= scale; v.w *= scale;
    ((float4*)(g_x + (size_t)node * F))[lane] = v;
    float4 wv = ((const float4*)wa)[lane];
    float a = v.x * wv.x + v.y * wv.y + v.z * wv.z + v.w * wv.w;
    #pragma unroll
    for (int o = 16; o > 0; o >>= 1) a += __shfl_xor_sync(0xffffffffu, a, o);
    if (lane == 0) g_att[node] = a;
}

// ---------------- pooling: one block per graph (batch sorted, no atomics) --
__global__ void __launch_bounds__(128) k_pool() {
    int g  = blockIdx.x;
    int f  = threadIdx.x;
    int lo = g_goff[g], hi = g_goff[g + 1];
    float ws = 0.f, sm = 0.f, mx = -3.4e38f;
    for (int i = lo; i < hi; i++) {
        float v = g_x[(size_t)i * F + f];
        float a = g_att[i];
        ws += a * v;
        sm += v;
        mx = fmaxf(mx, v);
    }
    float cnt = (float)(hi - lo > 0 ? hi - lo : 1);
    if (hi <= lo) mx = 0.f;                   // isfinite -> 0 for empty graphs
    float* rp = g_rep + (size_t)g * (3 * F);
    rp[f]         += ws;
    rp[F + f]     += sm / cnt;
    rp[2 * F + f] += mx;
}

// ---------------- head: MLP + log_softmax, one block per graph -------------
__global__ void __launch_bounds__(128) k_head(const float* __restrict__ w1,
                                              const float* __restrict__ b1,
                                              const float* __restrict__ w2,
                                              const float* __restrict__ b2,
                                              float* __restrict__ out) {
    __shared__ float rep[3 * F];
    __shared__ float h1[F];
    __shared__ float lg[NCLS];
    int g = blockIdx.x, t = threadIdx.x;
    for (int i = t; i < 3 * F; i += 128) rep[i] = g_rep[(size_t)g * (3 * F) + i];
    __syncthreads();
    float acc = b1[t];
    #pragma unroll 8
    for (int k = 0; k < 3 * F; k++) acc += rep[k] * w1[(size_t)k * F + t];
    h1[t] = fmaxf(acc, 0.f);
    __syncthreads();
    if (t < NCLS) {
        float a = b2[t];
        #pragma unroll 8
        for (int k = 0; k < F; k++) a += h1[k] * w2[(size_t)k * NCLS + t];
        lg[t] = a;
    }
    __syncthreads();
    if (t == 0) {
        float mx = lg[0];
        for (int c = 1; c < NCLS; c++) mx = fmaxf(mx, lg[c]);
        float se = 0.f;
        for (int c = 0; c < NCLS; c++) se += expf(lg[c] - mx);
        float lse = mx + logf(se);
        for (int c = 0; c < NCLS; c++) out[g * NCLS + c] = lg[c] - lse;
    }
}

// ---------------- launch ----------------------------------------------------
extern "C" void kernel_launch(void* const* d_in, const int* in_sizes, int n_in,
                              void* d_out, int out_size) {
    const float* x      = (const float*)d_in[0];
    const void*  edge   = d_in[1];
    const void*  batch  = d_in[2];
    const float* bn_g   = (const float*)d_in[3];
    const float* bn_b   = (const float*)d_in[4];
    const float* gcn_w  = (const float*)d_in[5];
    const float* gcn_b  = (const float*)d_in[6];
    const float* w_att  = (const float*)d_in[7];
    const float* lin1_w = (const float*)d_in[8];
    const float* lin1_b = (const float*)d_in[9];
    const float* lin2_w = (const float*)d_in[10];
    const float* lin2_b = (const float*)d_in[11];
    float* out = (float*)d_out;

    k_detect<<<1, 1>>>(edge, batch);
    k_init<<<(NG * 3 * F + 255) / 256, 256>>>();
    k_bnstats<<<(N_NODES + 255) / 256, 128>>>(x);
    k_deg<<<(NE + 255) / 256, 256>>>(edge);
    k_bnapply<<<(N_NODES * 32 + 255) / 256, 256>>>(x, bn_g, bn_b);
    k_goff<<<2, 256>>>(batch);

    for (int l = 0; l < NLAYERS; l++) {
        const float* W  = gcn_w + (size_t)l * F * F;
        const float* b  = gcn_b + (size_t)l * F;
        const float* wa = w_att + (size_t)l * F;
        k_gemm<<<(N_NODES + BM - 1) / BM, 256>>>(W);
        k_scatter<<<(NE * 32 + 255) / 256, 256>>>(edge);
        k_squash<<<(N_NODES * 32 + 255) / 256, 256>>>(b, wa);
        k_pool<<<NG, 128>>>();
    }
    k_head<<<NG, 128>>>(lin1_w, lin1_b, lin2_w, lin2_b, out);
}

// round 6
// speedup vs baseline: 1.3265x; 1.3265x over previous
#include <cuda_runtime.h>
#include <cstdint>

#define N_NODES 50000
#define NE      640000
#define F       128
#define NG      256
#define NCLS    10
#define NLAYERS 3
#define NSCANB  ((N_NODES + 255) / 256)   // 196 scan blocks

// ---------------- scratch (static device globals; no allocations) ----------
__device__ __align__(16) float g_x [N_NODES * F];    // working node features
__device__ __align__(16) float g_h [N_NODES * F];    // GEMM output
__device__ float g_att [N_NODES];
__device__ float g_dinv[N_NODES];
__device__ int   g_cnt [N_NODES];                    // in-degree (no self loop)
__device__ int   g_coff[N_NODES + 1];                // CSR row offsets (by dst)
__device__ int   g_cur [N_NODES];                    // placement cursors
__device__ int   g_csrc[NE];                         // CSR col = src node
__device__ float g_cw  [NE];                         // edge weight dinv_s*dinv_d
__device__ int   g_bsum[NSCANB];
__device__ int   g_boff[NSCANB];
__device__ float g_colsum[F];
__device__ float g_colsq [F];
__device__ float g_rep[NG * 3 * F];
__device__ int   g_goff[NG + 1];
__device__ int   g_is64_edge;
__device__ int   g_is64_batch;

// ---------------- index dtype detection ------------------------------------
// JAX may silently downcast requested int64 -> int32. Element counts match
// either way, so probe values: int32 data read as int64 fuses two random ids
// -> out of [0,N) with overwhelming probability over 8 samples.
__global__ void k_detect(const void* edge, const void* batch) {
    int ok = 1;
    for (int t = 0; t < 8; t++) {
        long long v = ((const long long*)edge)[t * 79999 + 7];  // < 640000
        if (v < 0 || v >= N_NODES) ok = 0;
    }
    g_is64_edge = ok;
    int okb = 1;
    for (int t = 0; t < 8; t++) {
        long long v = ((const long long*)batch)[12000 + t * 137];  // < 25000
        if (v < 0 || v >= NG) okb = 0;
    }
    g_is64_batch = okb;
}

__device__ __forceinline__ int ldidx(const void* p, long long i, int is64) {
    return is64 ? (int)((const long long*)p)[i] : ((const int*)p)[i];
}

// ---------------- init ------------------------------------------------------
__global__ void k_init() {
    int i = blockIdx.x * blockDim.x + threadIdx.x;
    if (i < F) { g_colsum[i] = 0.f; g_colsq[i] = 0.f; }
    if (i < NG * 3 * F) g_rep[i] = 0.f;
    if (i < N_NODES) g_cnt[i] = 0;
}

// ---------------- BN column stats ------------------------------------------
__global__ void k_bnstats(const float* __restrict__ X) {
    int f  = threadIdx.x;          // 128 threads = feature
    int r0 = blockIdx.x * 256;
    float s = 0.f, q = 0.f;
    for (int r = 0; r < 256; r++) {
        int row = r0 + r;
        if (row >= N_NODES) break;
        float v = X[(size_t)row * F + f];
        s += v; q += v * v;
    }
    atomicAdd(&g_colsum[f], s);
    atomicAdd(&g_colsq[f], q);
}

// ---------------- in-degree count (excl self loops) ------------------------
__global__ void k_count(const void* edge) {
    int e = blockIdx.x * blockDim.x + threadIdx.x;
    if (e >= NE) return;
    int is64 = g_is64_edge;
    int s = ldidx(edge, e, is64);
    int d = ldidx(edge, (long long)NE + e, is64);
    if (s != d) atomicAdd(&g_cnt[d], 1);
}

// ---------------- BN apply (vectorized float4) -----------------------------
__global__ void k_bnapply(const float* __restrict__ X,
                          const float* __restrict__ gamma,
                          const float* __restrict__ beta) {
    int i = blockIdx.x * blockDim.x + threadIdx.x;   // float4 index
    const float invN = 1.0f / (float)N_NODES;
    if (i >= N_NODES * (F / 4)) return;
    int f0 = (i & 31) * 4;
    float4 v = ((const float4*)X)[i];
    float o[4]; float in[4] = {v.x, v.y, v.z, v.w};
    #pragma unroll
    for (int c = 0; c < 4; c++) {
        int f = f0 + c;
        float mu  = g_colsum[f] * invN;
        float var = g_colsq[f] * invN - mu * mu;
        o[c] = (in[c] - mu) / sqrtf(var + 1e-5f) * gamma[f] + beta[f];
    }
    ((float4*)g_x)[i] = make_float4(o[0], o[1], o[2], o[3]);
}

// ---------------- exclusive scan of g_cnt -> g_coff (3 kernels) ------------
__global__ void k_scan1() {
    __shared__ int sh[256];
    int i = blockIdx.x * 256 + threadIdx.x;
    int v = (i < N_NODES) ? g_cnt[i] : 0;
    sh[threadIdx.x] = v;
    __syncthreads();
    #pragma unroll
    for (int o = 1; o < 256; o <<= 1) {
        int t = (threadIdx.x >= o) ? sh[threadIdx.x - o] : 0;
        __syncthreads();
        sh[threadIdx.x] += t;
        __syncthreads();
    }
    if (i < N_NODES) g_coff[i] = sh[threadIdx.x] - v;   // exclusive in block
    if (threadIdx.x == 255) g_bsum[blockIdx.x] = sh[255];
}

__global__ void k_scan2() {
    __shared__ int sh[256];
    int t = threadIdx.x;
    int v = (t < NSCANB) ? g_bsum[t] : 0;
    sh[t] = v;
    __syncthreads();
    #pragma unroll
    for (int o = 1; o < 256; o <<= 1) {
        int u = (t >= o) ? sh[t - o] : 0;
        __syncthreads();
        sh[t] += u;
        __syncthreads();
    }
    if (t < NSCANB) g_boff[t] = sh[t] - v;
    if (t == 255) g_coff[N_NODES] = sh[255];            // total non-self edges
}

__global__ void k_scan3() {
    int i = blockIdx.x * 256 + threadIdx.x;
    if (i >= N_NODES) return;
    int c = g_coff[i] + g_boff[blockIdx.x];
    g_coff[i] = c;
    g_cur[i]  = c;
    g_dinv[i] = rsqrtf((float)g_cnt[i] + 1.0f);         // deg incl self loop
}

// ---------------- CSR placement with edge weights --------------------------
__global__ void k_place(const void* edge) {
    int e = blockIdx.x * blockDim.x + threadIdx.x;
    if (e >= NE) return;
    int is64 = g_is64_edge;
    int s = ldidx(edge, e, is64);
    int d = ldidx(edge, (long long)NE + e, is64);
    if (s == d) return;
    int pos = atomicAdd(&g_cur[d], 1);
    g_csrc[pos] = s;
    g_cw[pos]   = g_dinv[s] * g_dinv[d];
}

// ---------------- per-graph offsets (batch sorted) -------------------------
__global__ void k_goff(const void* batch) {
    int g = blockIdx.x * blockDim.x + threadIdx.x;
    if (g > NG) return;
    int is64 = g_is64_batch;
    int lo = 0, hi = N_NODES;
    while (lo < hi) {
        int mid = (lo + hi) >> 1;
        long long v = is64 ? ((const long long*)batch)[mid]
                           : (long long)((const int*)batch)[mid];
        if (v < g) lo = mid + 1; else hi = mid;
    }
    g_goff[g] = lo;
}

// ---------------- GEMM: g_h = g_x @ W  (M=50000, N=K=128, fp32) ------------
#define BM 64
__global__ void __launch_bounds__(256) k_gemm(const float* __restrict__ W) {
    __shared__ float Xs[BM * 128];   // 32 KB
    __shared__ float Ws[32 * 128];   // 16 KB
    int tid = threadIdx.x;
    int m0  = blockIdx.x * BM;

    {   // stage X tile
        const float4* src = (const float4*)(g_x + (size_t)m0 * F);
        float4* dst = (float4*)Xs;
        for (int i = tid; i < BM * 32; i += 256) {
            int row = i >> 5;
            float4 v = make_float4(0.f, 0.f, 0.f, 0.f);
            if (m0 + row < N_NODES) v = src[i];
            dst[i] = v;
        }
    }
    int tx = tid & 31, ty = tid >> 5;
    float acc[8][4];
    #pragma unroll
    for (int r = 0; r < 8; r++)
        #pragma unroll
        for (int c = 0; c < 4; c++) acc[r][c] = 0.f;

    for (int kc = 0; kc < 128; kc += 32) {
        __syncthreads();
        const float4* wsrc = (const float4*)(W + (size_t)kc * 128);
        float4* wdst = (float4*)Ws;
        for (int i = tid; i < 1024; i += 256) wdst[i] = wsrc[i];
        __syncthreads();
        #pragma unroll
        for (int k = 0; k < 32; k++) {
            float4 b = ((const float4*)Ws)[k * 32 + tx];
            #pragma unroll
            for (int r = 0; r < 8; r++) {
                float a = Xs[(ty * 8 + r) * 128 + kc + k];   // warp-broadcast
                acc[r][0] += a * b.x; acc[r][1] += a * b.y;
                acc[r][2] += a * b.z; acc[r][3] += a * b.w;
            }
        }
    }
    #pragma unroll
    for (int r = 0; r < 8; r++) {
        int row = m0 + ty * 8 + r;
        if (row < N_NODES)
            ((float4*)(g_h + (size_t)row * F))[tx] =
                make_float4(acc[r][0], acc[r][1], acc[r][2], acc[r][3]);
    }
}

// ------- gather + bias + squash + att: warp per node, atomic-free ----------
// Edge metadata staged cooperatively: lane i loads edge lo+i (coalesced),
// then shuffle-broadcast (src, w). 4-way unroll keeps 4 row loads in flight.
__global__ void __launch_bounds__(256) k_gather(const float* __restrict__ bias,
                                                const float* __restrict__ wa) {
    int node = (blockIdx.x * blockDim.x + threadIdx.x) >> 5;
    int lane = threadIdx.x & 31;
    if (node >= N_NODES) return;
    int lo = g_coff[node], hi = g_coff[node + 1];

    // self-loop term: dinv^2 * h[node]
    float di = g_dinv[node];
    float w0 = di * di;
    float4 v = ((const float4*)(g_h + (size_t)node * F))[lane];
    float4 acc = make_float4(v.x * w0, v.y * w0, v.z * w0, v.w * w0);

    for (int base = lo; base < hi; base += 32) {
        int n = hi - base; if (n > 32) n = 32;
        int   se = 0; float we = 0.f;
        if (lane < n) { se = g_csrc[base + lane]; we = g_cw[base + lane]; }
        int j = 0;
        for (; j + 3 < n; j += 4) {
            int   s0 = __shfl_sync(0xffffffffu, se, j);
            int   s1 = __shfl_sync(0xffffffffu, se, j + 1);
            int   s2 = __shfl_sync(0xffffffffu, se, j + 2);
            int   s3 = __shfl_sync(0xffffffffu, se, j + 3);
            float w1 = __shfl_sync(0xffffffffu, we, j);
            float w2 = __shfl_sync(0xffffffffu, we, j + 1);
            float w3 = __shfl_sync(0xffffffffu, we, j + 2);
            float w4 = __shfl_sync(0xffffffffu, we, j + 3);
            float4 a = ((const float4*)(g_h + (size_t)s0 * F))[lane];
            float4 b = ((const float4*)(g_h + (size_t)s1 * F))[lane];
            float4 c = ((const float4*)(g_h + (size_t)s2 * F))[lane];
            float4 d = ((const float4*)(g_h + (size_t)s3 * F))[lane];
            acc.x += w1 * a.x + w2 * b.x + w3 * c.x + w4 * d.x;
            acc.y += w1 * a.y + w2 * b.y + w3 * c.y + w4 * d.y;
            acc.z += w1 * a.z + w2 * b.z + w3 * c.z + w4 * d.z;
            acc.w += w1 * a.w + w2 * b.w + w3 * c.w + w4 * d.w;
        }
        for (; j < n; j++) {
            int   s0 = __shfl_sync(0xffffffffu, se, j);
            float w1 = __shfl_sync(0xffffffffu, we, j);
            float4 a = ((const float4*)(g_h + (size_t)s0 * F))[lane];
            acc.x += w1 * a.x; acc.y += w1 * a.y;
            acc.z += w1 * a.z; acc.w += w1 * a.w;
        }
    }

    // + bias, squash, attention score
    float4 bb = ((const float4*)bias)[lane];
    acc.x += bb.x; acc.y += bb.y; acc.z += bb.z; acc.w += bb.w;
    float n2 = acc.x * acc.x + acc.y * acc.y + acc.z * acc.z + acc.w * acc.w;
    #pragma unroll
    for (int o = 16; o > 0; o >>= 1) n2 += __shfl_xor_sync(0xffffffffu, n2, o);
    float scale = n2 / ((1.0f + n2) * sqrtf(n2 + 1e-8f));
    acc.x *= scale; acc.y *= scale; acc.z *= scale; acc.w *= scale;
    ((float4*)(g_x + (size_t)node * F))[lane] = acc;

    float4 wv = ((const float4*)wa)[lane];
    float a = acc.x * wv.x + acc.y * wv.y + acc.z * wv.z + acc.w * wv.w;
    #pragma unroll
    for (int o = 16; o > 0; o >>= 1) a += __shfl_xor_sync(0xffffffffu, a, o);
    if (lane == 0) g_att[node] = a;
}

// ---------------- pooling: one block per graph (batch sorted, no atomics) --
__global__ void __launch_bounds__(128) k_pool() {
    int g  = blockIdx.x;
    int f  = threadIdx.x;
    int lo = g_goff[g], hi = g_goff[g + 1];
    float ws = 0.f, sm = 0.f, mx = -3.4e38f;
    for (int i = lo; i < hi; i++) {
        float v = g_x[(size_t)i * F + f];
        float a = g_att[i];
        ws += a * v;
        sm += v;
        mx = fmaxf(mx, v);
    }
    float cnt = (float)(hi - lo > 0 ? hi - lo : 1);
    if (hi <= lo) mx = 0.f;                   // isfinite -> 0 for empty graphs
    float* rp = g_rep + (size_t)g * (3 * F);
    rp[f]         += ws;
    rp[F + f]     += sm / cnt;
    rp[2 * F + f] += mx;
}

// ---------------- head: MLP + log_softmax, one block per graph -------------
__global__ void __launch_bounds__(128) k_head(const float* __restrict__ w1,
                                              const float* __restrict__ b1,
                                              const float* __restrict__ w2,
                                              const float* __restrict__ b2,
                                              float* __restrict__ out) {
    __shared__ float rep[3 * F];
    __shared__ float h1[F];
    __shared__ float lg[NCLS];
    int g = blockIdx.x, t = threadIdx.x;
    for (int i = t; i < 3 * F; i += 128) rep[i] = g_rep[(size_t)g * (3 * F) + i];
    __syncthreads();
    float acc = b1[t];
    #pragma unroll 8
    for (int k = 0; k < 3 * F; k++) acc += rep[k] * w1[(size_t)k * F + t];
    h1[t] = fmaxf(acc, 0.f);
    __syncthreads();
    if (t < NCLS) {
        float a = b2[t];
        #pragma unroll 8
        for (int k = 0; k < F; k++) a += h1[k] * w2[(size_t)k * NCLS + t];
        lg[t] = a;
    }
    __syncthreads();
    if (t == 0) {
        float mx = lg[0];
        for (int c = 1; c < NCLS; c++) mx = fmaxf(mx, lg[c]);
        float se = 0.f;
        for (int c = 0; c < NCLS; c++) se += expf(lg[c] - mx);
        float lse = mx + logf(se);
        for (int c = 0; c < NCLS; c++) out[g * NCLS + c] = lg[c] - lse;
    }
}

// ---------------- launch ----------------------------------------------------
extern "C" void kernel_launch(void* const* d_in, const int* in_sizes, int n_in,
                              void* d_out, int out_size) {
    const float* x      = (const float*)d_in[0];
    const void*  edge   = d_in[1];
    const void*  batch  = d_in[2];
    const float* bn_g   = (const float*)d_in[3];
    const float* bn_b   = (const float*)d_in[4];
    const float* gcn_w  = (const float*)d_in[5];
    const float* gcn_b  = (const float*)d_in[6];
    const float* w_att  = (const float*)d_in[7];
    const float* lin1_w = (const float*)d_in[8];
    const float* lin1_b = (const float*)d_in[9];
    const float* lin2_w = (const float*)d_in[10];
    const float* lin2_b = (const float*)d_in[11];
    float* out = (float*)d_out;

    k_detect<<<1, 1>>>(edge, batch);
    k_init<<<(NG * 3 * F + 255) / 256, 256>>>();
    k_bnstats<<<(N_NODES + 255) / 256, 128>>>(x);
    k_count<<<(NE + 255) / 256, 256>>>(edge);
    k_bnapply<<<(N_NODES * 32 + 255) / 256, 256>>>(x, bn_g, bn_b);
    k_scan1<<<NSCANB, 256>>>();
    k_scan2<<<1, 256>>>();
    k_scan3<<<NSCANB, 256>>>();
    k_place<<<(NE + 255) / 256, 256>>>(edge);
    k_goff<<<2, 256>>>(batch);

    for (int l = 0; l < NLAYERS; l++) {
        const float* W  = gcn_w + (size_t)l * F * F;
        const float* b  = gcn_b + (size_t)l * F;
        const float* wa = w_att + (size_t)l * F;
        k_gemm<<<(N_NODES + BM - 1) / BM, 256>>>(W);
        k_gather<<<(N_NODES * 32 + 255) / 256, 256>>>(b, wa);
        k_pool<<<NG, 128>>>();
    }
    k_head<<<NG, 128>>>(lin1_w, lin1_b, lin2_w, lin2_b, out);
}

// round 12
// speedup vs baseline: 1.6466x; 1.2413x over previous
#include <cuda_runtime.h>
#include <cstdint>

#define N_NODES 50000
#define NE      640000
#define F       128
#define NG      256
#define NCLS    10
#define NLAYERS 3
#define NSCANB  ((N_NODES + 255) / 256)   // 196 scan blocks

// ---------------- scratch (static device globals; no allocations) ----------
__device__ __align__(16) float g_x [N_NODES * F];    // working node features
__device__ __align__(16) float g_h [N_NODES * F];    // GEMM output
__device__ float g_att [N_NODES];
__device__ float g_dinv[N_NODES];
__device__ int   g_cnt [N_NODES];                    // in-degree (no self loop)
__device__ int   g_coff[N_NODES + 1];                // CSR row offsets (by dst)
__device__ int   g_cur [N_NODES];                    // placement cursors
__device__ int   g_csrc[NE];                         // CSR col = src node
__device__ float g_cw  [NE];                         // edge weight dinv_s*dinv_d
__device__ int   g_bsum[NSCANB];
__device__ int   g_boff[NSCANB];
__device__ float g_colsum[F];
__device__ float g_colsq [F];
__device__ float g_rep[NG * 3 * F];
__device__ int   g_goff[NG + 1];
__device__ int   g_is64_edge;
__device__ int   g_is64_batch;

// ---------------- index dtype detection ------------------------------------
__global__ void k_detect(const void* edge, const void* batch) {
    int ok = 1;
    for (int t = 0; t < 8; t++) {
        long long v = ((const long long*)edge)[t * 79999 + 7];  // < 640000
        if (v < 0 || v >= N_NODES) ok = 0;
    }
    g_is64_edge = ok;
    int okb = 1;
    for (int t = 0; t < 8; t++) {
        long long v = ((const long long*)batch)[12000 + t * 137];  // < 25000
        if (v < 0 || v >= NG) okb = 0;
    }
    g_is64_batch = okb;
}

__device__ __forceinline__ int ldidx(const void* p, long long i, int is64) {
    return is64 ? (int)((const long long*)p)[i] : ((const int*)p)[i];
}

__device__ __forceinline__ float f2tf32(float x) {
    uint32_t r;
    asm("cvt.rna.tf32.f32 %0, %1;" : "=r"(r) : "f"(x));
    return __uint_as_float(r);
}

// ---------------- init ------------------------------------------------------
__global__ void k_init() {
    int i = blockIdx.x * blockDim.x + threadIdx.x;
    if (i < F) { g_colsum[i] = 0.f; g_colsq[i] = 0.f; }
    if (i < NG * 3 * F) g_rep[i] = 0.f;
    if (i < N_NODES) g_cnt[i] = 0;
}

// ---------------- BN column stats ------------------------------------------
__global__ void k_bnstats(const float* __restrict__ X) {
    int f  = threadIdx.x;          // 128 threads = feature
    int r0 = blockIdx.x * 256;
    float s = 0.f, q = 0.f;
    for (int r = 0; r < 256; r++) {
        int row = r0 + r;
        if (row >= N_NODES) break;
        float v = X[(size_t)row * F + f];
        s += v; q += v * v;
    }
    atomicAdd(&g_colsum[f], s);
    atomicAdd(&g_colsq[f], q);
}

// ---------------- in-degree count (excl self loops) ------------------------
__global__ void k_count(const void* edge) {
    int e = blockIdx.x * blockDim.x + threadIdx.x;
    if (e >= NE) return;
    int is64 = g_is64_edge;
    int s = ldidx(edge, e, is64);
    int d = ldidx(edge, (long long)NE + e, is64);
    if (s != d) atomicAdd(&g_cnt[d], 1);
}

// ---------------- BN apply (vectorized float4) -----------------------------
__global__ void k_bnapply(const float* __restrict__ X,
                          const float* __restrict__ gamma,
                          const float* __restrict__ beta) {
    int i = blockIdx.x * blockDim.x + threadIdx.x;   // float4 index
    const float invN = 1.0f / (float)N_NODES;
    if (i >= N_NODES * (F / 4)) return;
    int f0 = (i & 31) * 4;
    float4 v = ((const float4*)X)[i];
    float o[4]; float in[4] = {v.x, v.y, v.z, v.w};
    #pragma unroll
    for (int c = 0; c < 4; c++) {
        int f = f0 + c;
        float mu  = g_colsum[f] * invN;
        float var = g_colsq[f] * invN - mu * mu;
        o[c] = (in[c] - mu) / sqrtf(var + 1e-5f) * gamma[f] + beta[f];
    }
    ((float4*)g_x)[i] = make_float4(o[0], o[1], o[2], o[3]);
}

// ---------------- exclusive scan of g_cnt -> g_coff (3 kernels) ------------
__global__ void k_scan1() {
    __shared__ int sh[256];
    int i = blockIdx.x * 256 + threadIdx.x;
    int v = (i < N_NODES) ? g_cnt[i] : 0;
    sh[threadIdx.x] = v;
    __syncthreads();
    #pragma unroll
    for (int o = 1; o < 256; o <<= 1) {
        int t = (threadIdx.x >= o) ? sh[threadIdx.x - o] : 0;
        __syncthreads();
        sh[threadIdx.x] += t;
        __syncthreads();
    }
    if (i < N_NODES) g_coff[i] = sh[threadIdx.x] - v;   // exclusive in block
    if (threadIdx.x == 255) g_bsum[blockIdx.x] = sh[255];
}

__global__ void k_scan2() {
    __shared__ int sh[256];
    int t = threadIdx.x;
    int v = (t < NSCANB) ? g_bsum[t] : 0;
    sh[t] = v;
    __syncthreads();
    #pragma unroll
    for (int o = 1; o < 256; o <<= 1) {
        int u = (t >= o) ? sh[t - o] : 0;
        __syncthreads();
        sh[t] += u;
        __syncthreads();
    }
    if (t < NSCANB) g_boff[t] = sh[t] - v;
    if (t == 255) g_coff[N_NODES] = sh[255];            // total non-self edges
}

__global__ void k_scan3() {
    int i = blockIdx.x * 256 + threadIdx.x;
    if (i >= N_NODES) return;
    int c = g_coff[i] + g_boff[blockIdx.x];
    g_coff[i] = c;
    g_cur[i]  = c;
    g_dinv[i] = rsqrtf((float)g_cnt[i] + 1.0f);         // deg incl self loop
}

// ---------------- CSR placement with edge weights --------------------------
__global__ void k_place(const void* edge) {
    int e = blockIdx.x * blockDim.x + threadIdx.x;
    if (e >= NE) return;
    int is64 = g_is64_edge;
    int s = ldidx(edge, e, is64);
    int d = ldidx(edge, (long long)NE + e, is64);
    if (s == d) return;
    int pos = atomicAdd(&g_cur[d], 1);
    g_csrc[pos] = s;
    g_cw[pos]   = g_dinv[s] * g_dinv[d];
}

// ---------------- per-graph offsets (batch sorted) -------------------------
__global__ void k_goff(const void* batch) {
    int g = blockIdx.x * blockDim.x + threadIdx.x;
    if (g > NG) return;
    int is64 = g_is64_batch;
    int lo = 0, hi = N_NODES;
    while (lo < hi) {
        int mid = (lo + hi) >> 1;
        long long v = is64 ? ((const long long*)batch)[mid]
                           : (long long)((const int*)batch)[mid];
        if (v < g) lo = mid + 1; else hi = mid;
    }
    g_goff[g] = lo;
}

// ------- GEMM: g_h = g_x @ W via tf32 mma.sync (m16n8k8, fp32 acc) ---------
// Block: 256 thr = 8 warps. BM=64 rows. Warp (wy,wx): rows wy*16+[0,16),
// cols wx*64+[0,64) as 8 n-tiles of 8. W staged 16 k-rows at a time.
// Smem strides padded for conflict-free fragment loads (Xs 132, Ws 136).
#define BM        64
#define XS_STRIDE 132
#define WS_STRIDE 136
__global__ void __launch_bounds__(256) k_gemm(const float* __restrict__ W) {
    __shared__ float Xs[BM * XS_STRIDE];   // 33.8 KB
    __shared__ float Ws[16 * WS_STRIDE];   //  8.7 KB
    int tid  = threadIdx.x;
    int m0   = blockIdx.x * BM;
    int warp = tid >> 5, lane = tid & 31;
    int wy = warp >> 1, wx = warp & 1;
    int grp = lane >> 2, qid = lane & 3;

    // stage Xs (tf32-rounded)
    for (int i = tid; i < BM * 32; i += 256) {
        int row = i >> 5, c4 = (i & 31) * 4;
        float4 v = make_float4(0.f, 0.f, 0.f, 0.f);
        if (m0 + row < N_NODES)
            v = ((const float4*)(g_x + (size_t)(m0 + row) * F))[i & 31];
        float* d = Xs + row * XS_STRIDE + c4;
        d[0] = f2tf32(v.x); d[1] = f2tf32(v.y);
        d[2] = f2tf32(v.z); d[3] = f2tf32(v.w);
    }

    float c[8][4];
    #pragma unroll
    for (int t = 0; t < 8; t++)
        #pragma unroll
        for (int j = 0; j < 4; j++) c[t][j] = 0.f;

    for (int kk = 0; kk < 128; kk += 16) {
        __syncthreads();
        // stage 16 k-rows of W (tf32-rounded)
        for (int i = tid; i < 16 * 32; i += 256) {
            int row = i >> 5, c4 = (i & 31) * 4;
            float4 v = ((const float4*)(W + (size_t)(kk + row) * F))[i & 31];
            float* d = Ws + row * WS_STRIDE + c4;
            d[0] = f2tf32(v.x); d[1] = f2tf32(v.y);
            d[2] = f2tf32(v.z); d[3] = f2tf32(v.w);
        }
        __syncthreads();
        #pragma unroll
        for (int ks = 0; ks < 16; ks += 8) {
            int arow = wy * 16 + grp;
            int kcol = kk + ks + qid;
            float a0 = Xs[arow * XS_STRIDE + kcol];
            float a1 = Xs[(arow + 8) * XS_STRIDE + kcol];
            float a2 = Xs[arow * XS_STRIDE + kcol + 4];
            float a3 = Xs[(arow + 8) * XS_STRIDE + kcol + 4];
            #pragma unroll
            for (int t = 0; t < 8; t++) {
                int col = wx * 64 + t * 8 + grp;
                float b0 = Ws[(ks + qid) * WS_STRIDE + col];
                float b1 = Ws[(ks + 4 + qid) * WS_STRIDE + col];
                asm volatile(
                    "mma.sync.aligned.m16n8k8.row.col.f32.tf32.tf32.f32 "
                    "{%0,%1,%2,%3}, {%4,%5,%6,%7}, {%8,%9}, {%0,%1,%2,%3};"
                    : "+f"(c[t][0]), "+f"(c[t][1]), "+f"(c[t][2]), "+f"(c[t][3])
                    : "r"(__float_as_uint(a0)), "r"(__float_as_uint(a1)),
                      "r"(__float_as_uint(a2)), "r"(__float_as_uint(a3)),
                      "r"(__float_as_uint(b0)), "r"(__float_as_uint(b1)));
            }
        }
    }

    // epilogue: c0,c1 -> (row, col..col+1); c2,c3 -> (row+8, ...)
    int row0 = m0 + wy * 16 + grp;
    #pragma unroll
    for (int t = 0; t < 8; t++) {
        int col = wx * 64 + t * 8 + qid * 2;
        if (row0 < N_NODES)
            *(float2*)(g_h + (size_t)row0 * F + col) = make_float2(c[t][0], c[t][1]);
        if (row0 + 8 < N_NODES)
            *(float2*)(g_h + (size_t)(row0 + 8) * F + col) = make_float2(c[t][2], c[t][3]);
    }
}

// ------- gather + bias + squash + att: warp per node, atomic-free ----------
__global__ void __launch_bounds__(256) k_gather(const float* __restrict__ bias,
                                                const float* __restrict__ wa) {
    int node = (blockIdx.x * blockDim.x + threadIdx.x) >> 5;
    int lane = threadIdx.x & 31;
    if (node >= N_NODES) return;
    int lo = g_coff[node], hi = g_coff[node + 1];

    // self-loop term: dinv^2 * h[node]
    float di = g_dinv[node];
    float w0 = di * di;
    float4 v = ((const float4*)(g_h + (size_t)node * F))[lane];
    float4 acc = make_float4(v.x * w0, v.y * w0, v.z * w0, v.w * w0);

    for (int base = lo; base < hi; base += 32) {
        int n = hi - base; if (n > 32) n = 32;
        int   se = 0; float we = 0.f;
        if (lane < n) { se = g_csrc[base + lane]; we = g_cw[base + lane]; }
        int j = 0;
        for (; j + 3 < n; j += 4) {
            int   s0 = __shfl_sync(0xffffffffu, se, j);
            int   s1 = __shfl_sync(0xffffffffu, se, j + 1);
            int   s2 = __shfl_sync(0xffffffffu, se, j + 2);
            int   s3 = __shfl_sync(0xffffffffu, se, j + 3);
            float w1 = __shfl_sync(0xffffffffu, we, j);
            float w2 = __shfl_sync(0xffffffffu, we, j + 1);
            float w3 = __shfl_sync(0xffffffffu, we, j + 2);
            float w4 = __shfl_sync(0xffffffffu, we, j + 3);
            float4 a = ((const float4*)(g_h + (size_t)s0 * F))[lane];
            float4 b = ((const float4*)(g_h + (size_t)s1 * F))[lane];
            float4 c = ((const float4*)(g_h + (size_t)s2 * F))[lane];
            float4 d = ((const float4*)(g_h + (size_t)s3 * F))[lane];
            acc.x += w1 * a.x + w2 * b.x + w3 * c.x + w4 * d.x;
            acc.y += w1 * a.y + w2 * b.y + w3 * c.y + w4 * d.y;
            acc.z += w1 * a.z + w2 * b.z + w3 * c.z + w4 * d.z;
            acc.w += w1 * a.w + w2 * b.w + w3 * c.w + w4 * d.w;
        }
        for (; j < n; j++) {
            int   s0 = __shfl_sync(0xffffffffu, se, j);
            float w1 = __shfl_sync(0xffffffffu, we, j);
            float4 a = ((const float4*)(g_h + (size_t)s0 * F))[lane];
            acc.x += w1 * a.x; acc.y += w1 * a.y;
            acc.z += w1 * a.z; acc.w += w1 * a.w;
        }
    }

    // + bias, squash, attention score
    float4 bb = ((const float4*)bias)[lane];
    acc.x += bb.x; acc.y += bb.y; acc.z += bb.z; acc.w += bb.w;
    float n2 = acc.x * acc.x + acc.y * acc.y + acc.z * acc.z + acc.w * acc.w;
    #pragma unroll
    for (int o = 16; o > 0; o >>= 1) n2 += __shfl_xor_sync(0xffffffffu, n2, o);
    float scale = n2 / ((1.0f + n2) * sqrtf(n2 + 1e-8f));
    acc.x *= scale; acc.y *= scale; acc.z *= scale; acc.w *= scale;
    ((float4*)(g_x + (size_t)node * F))[lane] = acc;

    float4 wv = ((const float4*)wa)[lane];
    float a = acc.x * wv.x + acc.y * wv.y + acc.z * wv.z + acc.w * wv.w;
    #pragma unroll
    for (int o = 16; o > 0; o >>= 1) a += __shfl_xor_sync(0xffffffffu, a, o);
    if (lane == 0) g_att[node] = a;
}

// ---------------- pooling: one block per graph (batch sorted, no atomics) --
__global__ void __launch_bounds__(128) k_pool() {
    int g  = blockIdx.x;
    int f  = threadIdx.x;
    int lo = g_goff[g], hi = g_goff[g + 1];
    float ws = 0.f, sm = 0.f, mx = -3.4e38f;
    for (int i = lo; i < hi; i++) {
        float v = g_x[(size_t)i * F + f];
        float a = g_att[i];
        ws += a * v;
        sm += v;
        mx = fmaxf(mx, v);
    }
    float cnt = (float)(hi - lo > 0 ? hi - lo : 1);
    if (hi <= lo) mx = 0.f;                   // isfinite -> 0 for empty graphs
    float* rp = g_rep + (size_t)g * (3 * F);
    rp[f]         += ws;
    rp[F + f]     += sm / cnt;
    rp[2 * F + f] += mx;
}

// ---------------- head: MLP + log_softmax, one block per graph -------------
__global__ void __launch_bounds__(128) k_head(const float* __restrict__ w1,
                                              const float* __restrict__ b1,
                                              const float* __restrict__ w2,
                                              const float* __restrict__ b2,
                                              float* __restrict__ out) {
    __shared__ float rep[3 * F];
    __shared__ float h1[F];
    __shared__ float lg[NCLS];
    int g = blockIdx.x, t = threadIdx.x;
    for (int i = t; i < 3 * F; i += 128) rep[i] = g_rep[(size_t)g * (3 * F) + i];
    __syncthreads();
    float acc = b1[t];
    #pragma unroll 8
    for (int k = 0; k < 3 * F; k++) acc += rep[k] * w1[(size_t)k * F + t];
    h1[t] = fmaxf(acc, 0.f);
    __syncthreads();
    if (t < NCLS) {
        float a = b2[t];
        #pragma unroll 8
        for (int k = 0; k < F; k++) a += h1[k] * w2[(size_t)k * NCLS + t];
        lg[t] = a;
    }
    __syncthreads();
    if (t == 0) {
        float mx = lg[0];
        for (int c = 1; c < NCLS; c++) mx = fmaxf(mx, lg[c]);
        float se = 0.f;
        for (int c = 0; c < NCLS; c++) se += expf(lg[c] - mx);
        float lse = mx + logf(se);
        for (int c = 0; c < NCLS; c++) out[g * NCLS + c] = lg[c] - lse;
    }
}

// ---------------- launch ----------------------------------------------------
extern "C" void kernel_launch(void* const* d_in, const int* in_sizes, int n_in,
                              void* d_out, int out_size) {
    const float* x      = (const float*)d_in[0];
    const void*  edge   = d_in[1];
    const void*  batch  = d_in[2];
    const float* bn_g   = (const float*)d_in[3];
    const float* bn_b   = (const float*)d_in[4];
    const float* gcn_w  = (const float*)d_in[5];
    const float* gcn_b  = (const float*)d_in[6];
    const float* w_att  = (const float*)d_in[7];
    const float* lin1_w = (const float*)d_in[8];
    const float* lin1_b = (const float*)d_in[9];
    const float* lin2_w = (const float*)d_in[10];
    const float* lin2_b = (const float*)d_in[11];
    float* out = (float*)d_out;

    k_detect<<<1, 1>>>(edge, batch);
    k_init<<<(NG * 3 * F + 255) / 256, 256>>>();
    k_bnstats<<<(N_NODES + 255) / 256, 128>>>(x);
    k_count<<<(NE + 255) / 256, 256>>>(edge);
    k_bnapply<<<(N_NODES * 32 + 255) / 256, 256>>>(x, bn_g, bn_b);
    k_scan1<<<NSCANB, 256>>>();
    k_scan2<<<1, 256>>>();
    k_scan3<<<NSCANB, 256>>>();
    k_place<<<(NE + 255) / 256, 256>>>(edge);
    k_goff<<<2, 256>>>(batch);

    for (int l = 0; l < NLAYERS; l++) {
        const float* W  = gcn_w + (size_t)l * F * F;
        const float* b  = gcn_b + (size_t)l * F;
        const float* wa = w_att + (size_t)l * F;
        k_gemm<<<(N_NODES + BM - 1) / BM, 256>>>(W);
        k_gather<<<(N_NODES * 32 + 255) / 256, 256>>>(b, wa);
        k_pool<<<NG, 128>>>();
    }
    k_head<<<NG, 128>>>(lin1_w, lin1_b, lin2_w, lin2_b, out);
}